// round 8
// baseline (speedup 1.0000x reference)
#include <cuda_runtime.h>
#include <cuda_bf16.h>

// Problem constants (HungarianMatcher: B=16, Q=900, C=92, T=1600)
#define BQ   14400      // B*Q
#define NC   92         // num classes
#define NT   1600       // num targets

#define QT   36         // queries per block tile (14400 = 400*36)
#define THREADS 800     // 25 warps; each thread owns 2 targets -> all 1600 t

// ---------------------------------------------------------------------------
// Per-pair cost (proven R4 math, rel_err 5e-8). Enclosing-box identity:
//   ew = (wp + wt) - iwu   (max(a,b)+min(a,b) = a+b)
// ---------------------------------------------------------------------------
__device__ __forceinline__ float pair_cost(
        float4 pc, float4 pxy, float area_p,
        float tx0, float ty0, float tx1, float ty1,
        float tcx, float tcy, float tw, float th,
        float area_t, float nprob) {
    float ax  = fmaxf(pxy.x, tx0);
    float bx  = fminf(pxy.z, tx1);
    float iwu = bx - ax;                       // unclamped intersection w
    float ay  = fmaxf(pxy.y, ty0);
    float by  = fminf(pxy.w, ty1);
    float ihu = by - ay;

    float iw = fmaxf(iwu, 0.0f);
    float ih = fmaxf(ihu, 0.0f);
    float inter = iw * ih;

    float ew  = (pc.z + tw) - iwu;             // enclosing w via identity
    float eh  = (pc.w + th) - ihu;
    float enc = ew * eh;

    float uni = (area_p + area_t) - inter;
    float emu = enc - uni;
    float num = fmaf(inter, enc, -emu * uni);  // inter*enc - (enc-uni)*uni
    float giou = __fdividef(num, uni * enc);

    float cb = fabsf(pc.x - tcx) + fabsf(pc.y - tcy)
             + fabsf(pc.z - tw)  + fabsf(pc.w - th);

    return fmaf(5.0f, cb, fmaf(-2.0f, giou, nprob));
}

// ---------------------------------------------------------------------------
// Fused kernel: per-block softmax of its 36 query rows + pair costs.
// grid = 400 (one block per q-tile), block = 800 threads (2 targets each).
// Phase 1: warps 0..24 softmax rows w, w+25 of the tile into s_prob
//          (vectorized: 92 floats = 23 float4, lanes 0..22).
// Phase 2: R4-proven mainloop over QT queries from shared.
// ---------------------------------------------------------------------------
__global__ __launch_bounds__(THREADS, 2) void fused_cost_kernel(
        const float* __restrict__ pred_logits,  // [BQ,92]
        const float* __restrict__ pred_boxes,   // [BQ,4] cxcywh
        const int*   __restrict__ tgt_labels,   // [NT] int32
        const float* __restrict__ tgt_boxes,    // [NT,4] cxcywh
        float*       __restrict__ out) {
    __shared__ float4 s_xy[QT];            // pred xyxy
    __shared__ float4 s_cw[QT];            // pred cxcywh
    __shared__ float  s_prob[QT * NC];     // softmax rows for this q-tile

    const int tid  = threadIdx.x;
    const int warp = tid >> 5;
    const int lane = tid & 31;
    const int q0   = blockIdx.x * QT;

    // ---- Phase 1a: softmax rows (warp per row; rows w and w+25) ----
    {
        const bool act = lane < 23;        // 23 float4 cover 92 floats
        for (int row = warp; row < QT; row += 25) {
            const float4* in = reinterpret_cast<const float4*>(
                pred_logits + (size_t)(q0 + row) * NC);
            float4 v = act ? in[lane]
                           : make_float4(-1e30f, -1e30f, -1e30f, -1e30f);

            float m = fmaxf(fmaxf(v.x, v.y), fmaxf(v.z, v.w));
            #pragma unroll
            for (int o = 16; o; o >>= 1)
                m = fmaxf(m, __shfl_xor_sync(0xffffffffu, m, o));

            float4 e = make_float4(__expf(v.x - m), __expf(v.y - m),
                                   __expf(v.z - m), __expf(v.w - m));
            float s = (e.x + e.y) + (e.z + e.w);
            #pragma unroll
            for (int o = 16; o; o >>= 1)
                s += __shfl_xor_sync(0xffffffffu, s, o);

            float r = __fdividef(1.0f, s);
            if (act) {
                float4* sp = reinterpret_cast<float4*>(s_prob + row * NC);
                sp[lane] = make_float4(e.x * r, e.y * r, e.z * r, e.w * r);
            }
        }
    }

    // ---- Phase 1b: pred box precompute ----
    if (tid < QT) {
        float4 b = reinterpret_cast<const float4*>(pred_boxes)[q0 + tid];
        s_cw[tid] = b;
        s_xy[tid] = make_float4(b.x - 0.5f * b.z, b.y - 0.5f * b.w,
                                b.x + 0.5f * b.z, b.y + 0.5f * b.w);
    }
    __syncthreads();

    // ---- Phase 2: two adjacent targets per thread, loaded once ----
    const int t0 = 2 * tid;                                     // covers 0..1598
    float4 ta = reinterpret_cast<const float4*>(tgt_boxes)[t0];
    float4 tb = reinterpret_cast<const float4*>(tgt_boxes)[t0 + 1];
    int la = min(max(tgt_labels[t0],     0), NC - 1);
    int lb = min(max(tgt_labels[t0 + 1], 0), NC - 1);

    const float ax0 = ta.x - 0.5f * ta.z, ay0 = ta.y - 0.5f * ta.w;
    const float ax1 = ta.x + 0.5f * ta.z, ay1 = ta.y + 0.5f * ta.w;
    const float areaA = ta.z * ta.w;

    const float bx0 = tb.x - 0.5f * tb.z, by0 = tb.y - 0.5f * tb.w;
    const float bx1 = tb.x + 0.5f * tb.z, by1 = tb.y + 0.5f * tb.w;
    const float areaB = tb.z * tb.w;

    float2* outp = reinterpret_cast<float2*>(out + (size_t)q0 * NT + t0);

    #pragma unroll 6
    for (int j = 0; j < QT; j++) {
        float4 pxy = s_xy[j];              // warp-uniform LDS.128 broadcast
        float4 pc  = s_cw[j];
        float  area_p = pc.z * pc.w;       // shared by both pairs
        const float* pr = s_prob + j * NC;

        float c0 = pair_cost(pc, pxy, area_p, ax0, ay0, ax1, ay1,
                             ta.x, ta.y, ta.z, ta.w, areaA, -pr[la]);
        float c1 = pair_cost(pc, pxy, area_p, bx0, by0, bx1, by1,
                             tb.x, tb.y, tb.z, tb.w, areaB, -pr[lb]);

        outp[(size_t)j * (NT / 2)] = make_float2(c0, c1);
    }
}

// ---------------------------------------------------------------------------
extern "C" void kernel_launch(void* const* d_in, const int* in_sizes, int n_in,
                              void* d_out, int out_size) {
    const float* pred_logits = (const float*)d_in[0];  // [16,900,92]
    const float* pred_boxes  = (const float*)d_in[1];  // [16,900,4]
    const int*   tgt_labels  = (const int*)  d_in[2];  // [1600] int32
    const float* tgt_boxes   = (const float*)d_in[3];  // [1600,4]
    float*       out         = (float*)d_out;          // [16,900,1600]

    (void)in_sizes; (void)n_in; (void)out_size;

    // Single fused kernel: 400 blocks x 800 threads.
    fused_cost_kernel<<<BQ / QT, THREADS>>>(pred_logits, pred_boxes,
                                            tgt_labels, tgt_boxes, out);
}